// round 6
// baseline (speedup 1.0000x reference)
#include <cuda_runtime.h>
#include <cuda_fp16.h>

#define EMB 32
#define K 10
#define NPB 128      // nodes per block (32 per warp)
#define THREADS 128
#define PITCH 36     // fp32 comb row pitch (32 data + 4 pad), 16B-aligned rows

// fp16 feature tables (device globals: allocation-free scratch)
__device__ __half g_embh[500000 * EMB];   // 32 MB
__device__ __half g_h1h [500000 * EMB];   // 32 MB

// sm_103a packed fp32 pair FMA
__device__ __forceinline__ void ffma2(unsigned long long& acc,
                                      unsigned long long a, unsigned long long b)
{ asm("fma.rn.f32x2 %0, %1, %2, %0;" : "+l"(acc) : "l"(a), "l"(b)); }

// ---- fp32 -> fp16 table conversion (runs every call; deterministic) ----
__global__ __launch_bounds__(256)
void cvt_f32_to_f16(const float* __restrict__ src, __half* __restrict__ dst, int n4)
{
    int i = blockIdx.x * blockDim.x + threadIdx.x;
    int stride = gridDim.x * blockDim.x;
    const float4* s4 = reinterpret_cast<const float4*>(src);
    __half2* d2 = reinterpret_cast<__half2*>(dst);
    for (; i < n4; i += stride) {
        float4 v = s4[i];
        d2[2 * i]     = __floats2half2_rn(v.x, v.y);
        d2[2 * i + 1] = __floats2half2_rn(v.z, v.w);
    }
}

template<bool OUT_HALF>
__global__ __launch_bounds__(THREADS, 7)
void sage_layer_kernel(const __half* __restrict__ feat,     // [Nf, 32] fp16
                       const int*    __restrict__ node_ids, // [n] or nullptr
                       const int*    __restrict__ neigh,    // [N_NODES, K]
                       const float*  __restrict__ W,        // [32, 64] row-major
                       void*         __restrict__ outp,     // [n, 32] half or float
                       int n)
{
    __shared__ __align__(16) float Ws[32 * 64];          // 8 KB
    __shared__ __align__(16) float comb[NPB * PITCH];    // 18.4 KB

    const int tid   = threadIdx.x;
    const int lane  = tid & 31;
    const int wrp   = tid >> 5;
    const int grp8  = lane >> 2;        // 8 row-groups of 4 lanes (fp16 rows = 64B)
    const int c2    = lane & 3;         // 16B chunk within 64B row
    const int nbase = blockIdx.x * NPB + wrp * 32;
    const int myrow = wrp * 32 + lane;

    // ---- W into shared (coalesced); only block-wide sync ----
    #pragma unroll
    for (int x = tid; x < 32 * 64; x += THREADS)
        Ws[x] = W[x];
    __syncthreads();

    // ---- this lane's node id ----
    int g   = nbase + lane;
    int sid = (g < n) ? (node_ids ? node_ids[g] : g) : 0;

    float* crow = &comb[(wrp * 32) * PITCH];

    // ======== PHASE 1: mean aggregation (8 rows per LDG.128) ========
    #pragma unroll 2
    for (int pass = 0; pass < 4; ++pass) {
        int nd   = pass * 8 + grp8;
        int sidg = __shfl_sync(0xffffffffu, sid, nd);
        int nb[K];
        #pragma unroll
        for (int k = 0; k < K; k++)
            nb[k] = neigh[sidg * K + k];
        float acc[8] = {0,0,0,0,0,0,0,0};
        #pragma unroll
        for (int k = 0; k < K; k++) {       // 10 independent 16B loads in flight
            const __half2* p = reinterpret_cast<const __half2*>(
                                   feat + nb[k] * EMB) + c2 * 4;
            #pragma unroll
            for (int h = 0; h < 4; h++) {
                float2 f = __half22float2(p[h]);
                acc[2 * h]     += f.x;
                acc[2 * h + 1] += f.y;
            }
        }
        float4* dst = reinterpret_cast<float4*>(&crow[nd * PITCH + c2 * 8]);
        dst[0] = make_float4(acc[0] * 0.1f, acc[1] * 0.1f, acc[2] * 0.1f, acc[3] * 0.1f);
        dst[1] = make_float4(acc[4] * 0.1f, acc[5] * 0.1f, acc[6] * 0.1f, acc[7] * 0.1f);
    }
    __syncwarp();

    // ---- own agg row -> packed registers ----
    unsigned long long rc[32];   // [0..15]=self pairs, [16..31]=agg pairs
    {
        const unsigned long long* p =
            reinterpret_cast<const unsigned long long*>(&comb[myrow * PITCH]);
        #pragma unroll
        for (int i = 0; i < 16; i++) rc[16 + i] = p[i];
    }
    __syncwarp();

    // ======== PHASE 2: self rows (8 rows per LDG.128) ========
    #pragma unroll 2
    for (int pass = 0; pass < 4; ++pass) {
        int nd = pass * 8 + grp8;
        int s  = __shfl_sync(0xffffffffu, sid, nd);
        const __half2* p = reinterpret_cast<const __half2*>(feat + s * EMB) + c2 * 4;
        float4 a, b;
        { float2 f0 = __half22float2(p[0]), f1 = __half22float2(p[1]);
          a = make_float4(f0.x, f0.y, f1.x, f1.y); }
        { float2 f2 = __half22float2(p[2]), f3 = __half22float2(p[3]);
          b = make_float4(f2.x, f2.y, f3.x, f3.y); }
        float4* dst = reinterpret_cast<float4*>(&crow[nd * PITCH + c2 * 8]);
        dst[0] = a;
        dst[1] = b;
    }
    __syncwarp();
    {
        const unsigned long long* p =
            reinterpret_cast<const unsigned long long*>(&comb[myrow * PITCH]);
        #pragma unroll
        for (int i = 0; i < 16; i++) rc[i] = p[i];
    }
    // Thread-private from here.

    // ======== PHASE 3: matvec, packed dual-FMA (fp32) ========
    const ulonglong2* Wp = reinterpret_cast<const ulonglong2*>(Ws);
    #pragma unroll 4
    for (int j = 0; j < 32; j++) {
        unsigned long long acc2 = 0ull;
        #pragma unroll
        for (int i2 = 0; i2 < 16; i2++) {
            ulonglong2 w = Wp[j * 16 + i2];      // uniform LDS.128 broadcast
            ffma2(acc2, rc[2 * i2],     w.x);
            ffma2(acc2, rc[2 * i2 + 1], w.y);
        }
        float lo, hi;
        asm("mov.b64 {%0, %1}, %2;" : "=f"(lo), "=f"(hi) : "l"(acc2));
        comb[myrow * PITCH + j] = fmaxf(lo + hi, 0.f);
    }
    __syncwarp();

    // ======== PHASE 4: coalesced store ========
    if (OUT_HALF) {
        __half* out = reinterpret_cast<__half*>(outp);
        #pragma unroll
        for (int pass = 0; pass < 4; ++pass) {
            int nd = pass * 8 + grp8;
            int gg = nbase + nd;
            if (gg < n) {
                const float* src = &crow[nd * PITCH + c2 * 8];
                __half2 h[4];
                #pragma unroll
                for (int i = 0; i < 4; i++)
                    h[i] = __floats2half2_rn(src[2 * i], src[2 * i + 1]);
                // 4 x half2 = 16 bytes: full chunk (uint2 here was the R5 bug)
                *reinterpret_cast<uint4*>(out + gg * EMB + c2 * 8)
                    = *reinterpret_cast<const uint4*>(h);
            }
        }
    } else {
        float* out = reinterpret_cast<float*>(outp);
        int grp4 = lane >> 3, c4 = lane & 7;    // fp32 rows = 128B, 4 rows/STG.128
        #pragma unroll
        for (int it = 0; it < 8; ++it) {
            int nd = 4 * it + grp4;
            int gg = nbase + nd;
            if (gg < n) {
                float4 v = *reinterpret_cast<const float4*>(&crow[nd * PITCH + c4 * 4]);
                *reinterpret_cast<float4*>(&out[gg * EMB + c4 * 4]) = v;
            }
        }
    }
}

extern "C" void kernel_launch(void* const* d_in, const int* in_sizes, int n_in,
                              void* d_out, int out_size)
{
    // metadata order: emb, W1, W2, node_batch, neigh
    const float* emb        = (const float*)d_in[0];
    const float* W1         = (const float*)d_in[1];
    const float* W2         = (const float*)d_in[2];
    const int*   node_batch = (const int*)  d_in[3];
    const int*   neigh      = (const int*)  d_in[4];
    float*       out        = (float*)d_out;

    const int N = in_sizes[0] / EMB;   // 500000
    const int B = in_sizes[3];         // 100000

    __half *embh = nullptr, *h1h = nullptr;
    cudaGetSymbolAddress((void**)&embh, g_embh);
    cudaGetSymbolAddress((void**)&h1h,  g_h1h);

    // Prep: emb fp32 -> fp16 (keeps gather working set L2-resident)
    cvt_f32_to_f16<<<4096, 256>>>(emb, embh, N * EMB / 4);

    // Layer 1: h1h = relu([emb | mean(emb[neigh])] @ W1^T), stored fp16
    sage_layer_kernel<true><<<(N + NPB - 1) / NPB, THREADS>>>(
        embh, nullptr, neigh, W1, h1h, N);
    // Layer 2: out = relu([h1[nb] | mean(h1[neigh[nb]])] @ W2^T), fp32
    sage_layer_kernel<false><<<(B + NPB - 1) / NPB, THREADS>>>(
        h1h, node_batch, neigh, W2, out, B);
}

// round 7
// speedup vs baseline: 1.2274x; 1.2274x over previous
#include <cuda_runtime.h>
#include <cuda_fp16.h>

#define EMB 32
#define K 10
#define NPB 128      // nodes per block (32 per warp)
#define THREADS 128
#define PITCH 36     // fp32 comb row pitch (32 data + 4 pad), 16B-aligned rows

// fp16 feature tables (device globals: allocation-free scratch)
__device__ __align__(16) __half g_embh[500000 * EMB];   // 32 MB
__device__ __align__(16) __half g_h1h [500000 * EMB];   // 32 MB

// sm_103a packed fp32 pair FMA
__device__ __forceinline__ void ffma2(unsigned long long& acc,
                                      unsigned long long a, unsigned long long b)
{ asm("fma.rn.f32x2 %0, %1, %2, %0;" : "+l"(acc) : "l"(a), "l"(b)); }

// unpack 8 halves (one uint4) -> 8 floats
__device__ __forceinline__ void cvt8(uint4 v, float* f)
{
    const __half2* h = reinterpret_cast<const __half2*>(&v);
    #pragma unroll
    for (int i = 0; i < 4; i++) {
        float2 t = __half22float2(h[i]);
        f[2 * i]     = t.x;
        f[2 * i + 1] = t.y;
    }
}

// ---- fp32 -> fp16 table conversion (runs every call; deterministic) ----
__global__ __launch_bounds__(256)
void cvt_f32_to_f16(const float* __restrict__ src, __half* __restrict__ dst, int n4)
{
    int i = blockIdx.x * blockDim.x + threadIdx.x;
    int stride = gridDim.x * blockDim.x;
    const float4* s4 = reinterpret_cast<const float4*>(src);
    __half2* d2 = reinterpret_cast<__half2*>(dst);
    for (; i < n4; i += stride) {
        float4 v = s4[i];
        d2[2 * i]     = __floats2half2_rn(v.x, v.y);
        d2[2 * i + 1] = __floats2half2_rn(v.z, v.w);
    }
}

template<bool OUT_HALF>
__global__ __launch_bounds__(THREADS, 7)
void sage_layer_kernel(const __half* __restrict__ feat,     // [Nf, 32] fp16
                       const int*    __restrict__ node_ids, // [n] or nullptr
                       const int*    __restrict__ neigh,    // [N_NODES, K]
                       const float*  __restrict__ W,        // [32, 64] row-major
                       void*         __restrict__ outp,     // [n, 32] half or float
                       int n)
{
    __shared__ __align__(16) float Ws[32 * 64];          // 8 KB
    __shared__ __align__(16) float comb[NPB * PITCH];    // 18.4 KB

    const int tid   = threadIdx.x;
    const int lane  = tid & 31;
    const int wrp   = tid >> 5;
    const int grp8  = lane >> 2;        // 8 row-groups of 4 lanes (fp16 rows = 64B)
    const int c2    = lane & 3;         // 16B chunk within 64B row
    const int nbase = blockIdx.x * NPB + wrp * 32;
    const int myrow = wrp * 32 + lane;

    // ---- W into shared (coalesced); only block-wide sync ----
    #pragma unroll
    for (int x = tid; x < 32 * 64; x += THREADS)
        Ws[x] = W[x];
    __syncthreads();

    // ---- this lane's node id ----
    int g   = nbase + lane;
    int sid = (g < n) ? (node_ids ? node_ids[g] : g) : 0;

    float* crow = &comb[(wrp * 32) * PITCH];

    // ======== PHASE 1: mean aggregation — one LDG.128 per (lane, neighbor) ========
    #pragma unroll 2
    for (int pass = 0; pass < 4; ++pass) {
        int nd   = pass * 8 + grp8;
        int sidg = __shfl_sync(0xffffffffu, sid, nd);
        int nb[K];
        #pragma unroll
        for (int k = 0; k < K; k++)
            nb[k] = neigh[sidg * K + k];
        uint4 raw[K];
        #pragma unroll
        for (int k = 0; k < K; k++)          // 10 independent LDG.128 in flight
            raw[k] = *(reinterpret_cast<const uint4*>(feat + nb[k] * EMB) + c2);
        float acc[8] = {0,0,0,0,0,0,0,0};
        #pragma unroll
        for (int k = 0; k < K; k++) {
            float f[8];
            cvt8(raw[k], f);
            #pragma unroll
            for (int i = 0; i < 8; i++) acc[i] += f[i];
        }
        float4* dst = reinterpret_cast<float4*>(&crow[nd * PITCH + c2 * 8]);
        dst[0] = make_float4(acc[0] * 0.1f, acc[1] * 0.1f, acc[2] * 0.1f, acc[3] * 0.1f);
        dst[1] = make_float4(acc[4] * 0.1f, acc[5] * 0.1f, acc[6] * 0.1f, acc[7] * 0.1f);
    }
    __syncwarp();

    // ---- own agg row -> packed registers ----
    unsigned long long rc[32];   // [0..15]=self pairs, [16..31]=agg pairs
    {
        const unsigned long long* p =
            reinterpret_cast<const unsigned long long*>(&comb[myrow * PITCH]);
        #pragma unroll
        for (int i = 0; i < 16; i++) rc[16 + i] = p[i];
    }
    __syncwarp();

    // ======== PHASE 2: self rows — one LDG.128 per (lane, node-group) ========
    #pragma unroll 2
    for (int pass = 0; pass < 4; ++pass) {
        int nd = pass * 8 + grp8;
        int s  = __shfl_sync(0xffffffffu, sid, nd);
        uint4 raw = *(reinterpret_cast<const uint4*>(feat + s * EMB) + c2);
        float f[8];
        cvt8(raw, f);
        float4* dst = reinterpret_cast<float4*>(&crow[nd * PITCH + c2 * 8]);
        dst[0] = make_float4(f[0], f[1], f[2], f[3]);
        dst[1] = make_float4(f[4], f[5], f[6], f[7]);
    }
    __syncwarp();
    {
        const unsigned long long* p =
            reinterpret_cast<const unsigned long long*>(&comb[myrow * PITCH]);
        #pragma unroll
        for (int i = 0; i < 16; i++) rc[i] = p[i];
    }
    // Thread-private from here.

    // ======== PHASE 3: matvec, packed dual-FMA (fp32) ========
    const ulonglong2* Wp = reinterpret_cast<const ulonglong2*>(Ws);
    #pragma unroll 4
    for (int j = 0; j < 32; j++) {
        unsigned long long acc2 = 0ull;
        #pragma unroll
        for (int i2 = 0; i2 < 16; i2++) {
            ulonglong2 w = Wp[j * 16 + i2];      // uniform LDS.128 broadcast
            ffma2(acc2, rc[2 * i2],     w.x);
            ffma2(acc2, rc[2 * i2 + 1], w.y);
        }
        float lo, hi;
        asm("mov.b64 {%0, %1}, %2;" : "=f"(lo), "=f"(hi) : "l"(acc2));
        comb[myrow * PITCH + j] = fmaxf(lo + hi, 0.f);
    }
    __syncwarp();

    // ======== PHASE 4: coalesced store ========
    if (OUT_HALF) {
        __half* out = reinterpret_cast<__half*>(outp);
        #pragma unroll
        for (int pass = 0; pass < 4; ++pass) {
            int nd = pass * 8 + grp8;
            int gg = nbase + nd;
            if (gg < n) {
                const float* src = &crow[nd * PITCH + c2 * 8];
                __half2 h[4];
                #pragma unroll
                for (int i = 0; i < 4; i++)
                    h[i] = __floats2half2_rn(src[2 * i], src[2 * i + 1]);
                *reinterpret_cast<uint4*>(out + gg * EMB + c2 * 8)
                    = *reinterpret_cast<const uint4*>(h);   // 16B: full chunk
            }
        }
    } else {
        float* out = reinterpret_cast<float*>(outp);
        int grp4 = lane >> 3, c4 = lane & 7;    // fp32 rows = 128B, 4 rows/STG.128
        #pragma unroll
        for (int it = 0; it < 8; ++it) {
            int nd = 4 * it + grp4;
            int gg = nbase + nd;
            if (gg < n) {
                float4 v = *reinterpret_cast<const float4*>(&crow[nd * PITCH + c4 * 4]);
                *reinterpret_cast<float4*>(&out[gg * EMB + c4 * 4]) = v;
            }
        }
    }
}

extern "C" void kernel_launch(void* const* d_in, const int* in_sizes, int n_in,
                              void* d_out, int out_size)
{
    // metadata order: emb, W1, W2, node_batch, neigh
    const float* emb        = (const float*)d_in[0];
    const float* W1         = (const float*)d_in[1];
    const float* W2         = (const float*)d_in[2];
    const int*   node_batch = (const int*)  d_in[3];
    const int*   neigh      = (const int*)  d_in[4];
    float*       out        = (float*)d_out;

    const int N = in_sizes[0] / EMB;   // 500000
    const int B = in_sizes[3];         // 100000

    __half *embh = nullptr, *h1h = nullptr;
    cudaGetSymbolAddress((void**)&embh, g_embh);
    cudaGetSymbolAddress((void**)&h1h,  g_h1h);

    // Prep: emb fp32 -> fp16 (keeps gather working set L2-resident)
    cvt_f32_to_f16<<<4096, 256>>>(emb, embh, N * EMB / 4);

    // Layer 1: h1h = relu([emb | mean(emb[neigh])] @ W1^T), stored fp16
    sage_layer_kernel<true><<<(N + NPB - 1) / NPB, THREADS>>>(
        embh, nullptr, neigh, W1, h1h, N);
    // Layer 2: out = relu([h1[nb] | mean(h1[neigh[nb]])] @ W2^T), fp32
    sage_layer_kernel<false><<<(B + NPB - 1) / NPB, THREADS>>>(
        h1h, node_batch, neigh, W2, out, B);
}

// round 8
// speedup vs baseline: 1.3171x; 1.0730x over previous
#include <cuda_runtime.h>
#include <cuda_fp16.h>

#define EMB 32
#define K 10

// fp16 tables (device globals: allocation-free scratch)
__device__ __align__(16) __half g_embh[500000 * EMB];   // 32 MB
__device__ __align__(16) __half g_h1h [500000 * EMB];   // 32 MB
__device__ __align__(16) __half g_aggh[500096 * EMB];   // 32 MB (padded)

// sm_103a packed fp32 pair FMA
__device__ __forceinline__ void ffma2(unsigned long long& acc,
                                      unsigned long long a, unsigned long long b)
{ asm("fma.rn.f32x2 %0, %1, %2, %0;" : "+l"(acc) : "l"(a), "l"(b)); }

__device__ __forceinline__ unsigned long long pack2(float lo, float hi)
{ unsigned long long r; asm("mov.b64 %0, {%1, %2};" : "=l"(r) : "f"(lo), "f"(hi)); return r; }

// unpack 8 halves (one uint4) -> 8 floats
__device__ __forceinline__ void cvt8(uint4 v, float* f)
{
    const __half2* h = reinterpret_cast<const __half2*>(&v);
    #pragma unroll
    for (int i = 0; i < 4; i++) {
        float2 t = __half22float2(h[i]);
        f[2 * i]     = t.x;
        f[2 * i + 1] = t.y;
    }
}

// ---- fp32 -> fp16 table conversion ----
__global__ __launch_bounds__(256)
void cvt_f32_to_f16(const float* __restrict__ src, __half* __restrict__ dst, int n4)
{
    int i = blockIdx.x * blockDim.x + threadIdx.x;
    int stride = gridDim.x * blockDim.x;
    const float4* s4 = reinterpret_cast<const float4*>(src);
    __half2* d2 = reinterpret_cast<__half2*>(dst);
    for (; i < n4; i += stride) {
        float4 v = s4[i];
        d2[2 * i]     = __floats2half2_rn(v.x, v.y);
        d2[2 * i + 1] = __floats2half2_rn(v.z, v.w);
    }
}

// ======================================================================
// AGG kernel: agg[t] = mean_k feat[neigh[id(t)][k]]  (fp16 in / fp16 out)
// No smem, no block syncs: warps fully independent for latency hiding.
// ======================================================================
__global__ __launch_bounds__(128, 8)
void agg_kernel(const __half* __restrict__ feat,
                const int*    __restrict__ node_ids,   // nullptr -> identity
                const int*    __restrict__ neigh,
                __half*       __restrict__ agg,        // [>=n, 32]
                int n)
{
    const int lane  = threadIdx.x & 31;
    const int wrp   = threadIdx.x >> 5;
    const int grp8  = lane >> 2;     // 8 rows per warp step (fp16 row = 64B)
    const int c2    = lane & 3;      // 16B chunk within row
    const int nbase = blockIdx.x * 128 + wrp * 32;

    int g   = nbase + lane;
    int sid = (g < n) ? (node_ids ? node_ids[g] : g) : 0;

    for (int pass = 0; pass < 4; ++pass) {
        int nd   = pass * 8 + grp8;
        int sidg = __shfl_sync(0xffffffffu, sid, nd);
        int nb[K];
        #pragma unroll
        for (int k = 0; k < K; k++)
            nb[k] = neigh[sidg * K + k];
        uint4 raw[K];
        #pragma unroll
        for (int k = 0; k < K; k++)                 // 10 LDG.128 in flight
            raw[k] = *(reinterpret_cast<const uint4*>(feat + nb[k] * EMB) + c2);
        float acc[8] = {0,0,0,0,0,0,0,0};
        #pragma unroll
        for (int k = 0; k < K; k++) {
            float f[8];
            cvt8(raw[k], f);
            #pragma unroll
            for (int i = 0; i < 8; i++) acc[i] += f[i];
        }
        int gg = nbase + nd;
        if (gg < n) {
            __half2 h[4];
            #pragma unroll
            for (int i = 0; i < 4; i++)
                h[i] = __floats2half2_rn(acc[2 * i] * 0.1f, acc[2 * i + 1] * 0.1f);
            *(reinterpret_cast<uint4*>(agg + gg * EMB) + c2)
                = *reinterpret_cast<const uint4*>(h);
        }
    }
}

// ======================================================================
// MATVEC kernel: out[t] = relu(W @ [self | agg])   thread-per-node
// acc-outer: 16 packed j-pair accumulators; W as j-pair table in smem.
// ======================================================================
template<bool SELF_GATHER, bool OUT_HALF>
__global__ __launch_bounds__(256, 4)
void matvec_kernel(const __half* __restrict__ feat,      // self source [*, 32]
                   const __half* __restrict__ agg,       // [n, 32]
                   const int*    __restrict__ node_ids,  // used if SELF_GATHER
                   const float*  __restrict__ W,         // [32, 64]
                   void*         __restrict__ outp,
                   int n)
{
    // Wts[i][jp] = (W[2jp][i], W[2jp+1][i]) packed
    __shared__ __align__(16) unsigned long long Wts[64 * 16];   // 8 KB

    for (int e = threadIdx.x; e < 64 * 16; e += 256) {
        int i  = e & 63;
        int jp = e >> 6;
        Wts[i * 16 + jp] = pack2(W[(2 * jp) * 64 + i], W[(2 * jp + 1) * 64 + i]);
    }
    __syncthreads();

    int t = blockIdx.x * 256 + threadIdx.x;
    if (t >= n) return;

    const __half* selfp = SELF_GATHER ? (feat + (size_t)node_ids[t] * EMB)
                                      : (feat + (size_t)t * EMB);
    const __half* aggp  = agg + (size_t)t * EMB;

    // Prefetch both rows: 8 independent LDG.128
    uint4 s[4], a[4];
    #pragma unroll
    for (int c = 0; c < 4; c++) s[c] = reinterpret_cast<const uint4*>(selfp)[c];
    #pragma unroll
    for (int c = 0; c < 4; c++) a[c] = reinterpret_cast<const uint4*>(aggp)[c];

    unsigned long long acc2[16];
    #pragma unroll
    for (int jp = 0; jp < 16; jp++) acc2[jp] = 0ull;

    // process one uint4 chunk = 8 inputs starting at index ibase
    auto do_chunk = [&](uint4 v, int ibase) {
        const __half2* h = reinterpret_cast<const __half2*>(&v);
        #pragma unroll
        for (int q = 0; q < 4; q++) {
            float2 f = __half22float2(h[q]);
            int i = ibase + 2 * q;
            unsigned long long dx = pack2(f.x, f.x);
            unsigned long long dy = pack2(f.y, f.y);
            const ulonglong2* ra = reinterpret_cast<const ulonglong2*>(&Wts[i * 16]);
            const ulonglong2* rb = reinterpret_cast<const ulonglong2*>(&Wts[(i + 1) * 16]);
            #pragma unroll
            for (int jp2 = 0; jp2 < 8; jp2++) {
                ulonglong2 wa = ra[jp2];          // uniform LDS.128 broadcast
                ulonglong2 wb = rb[jp2];
                ffma2(acc2[2 * jp2],     dx, wa.x);
                ffma2(acc2[2 * jp2 + 1], dx, wa.y);
                ffma2(acc2[2 * jp2],     dy, wb.x);
                ffma2(acc2[2 * jp2 + 1], dy, wb.y);
            }
        }
    };

    #pragma unroll
    for (int c = 0; c < 4; c++) do_chunk(s[c], c * 8);        // self: i 0..31
    #pragma unroll
    for (int c = 0; c < 4; c++) do_chunk(a[c], 32 + c * 8);   // agg:  i 32..63

    if (OUT_HALF) {
        __half2 h[16];
        #pragma unroll
        for (int jp = 0; jp < 16; jp++) {
            float lo, hi;
            asm("mov.b64 {%0, %1}, %2;" : "=f"(lo), "=f"(hi) : "l"(acc2[jp]));
            h[jp] = __floats2half2_rn(fmaxf(lo, 0.f), fmaxf(hi, 0.f));
        }
        __half* out = reinterpret_cast<__half*>(outp);
        const uint4* hv = reinterpret_cast<const uint4*>(h);
        #pragma unroll
        for (int c = 0; c < 4; c++)
            reinterpret_cast<uint4*>(out + (size_t)t * EMB)[c] = hv[c];
    } else {
        float* out = reinterpret_cast<float*>(outp) + (size_t)t * EMB;
        #pragma unroll
        for (int jp = 0; jp < 16; jp++) {
            float lo, hi;
            asm("mov.b64 {%0, %1}, %2;" : "=f"(lo), "=f"(hi) : "l"(acc2[jp]));
            out[2 * jp]     = fmaxf(lo, 0.f);
            out[2 * jp + 1] = fmaxf(hi, 0.f);
        }
    }
}

extern "C" void kernel_launch(void* const* d_in, const int* in_sizes, int n_in,
                              void* d_out, int out_size)
{
    // metadata order: emb, W1, W2, node_batch, neigh
    const float* emb        = (const float*)d_in[0];
    const float* W1         = (const float*)d_in[1];
    const float* W2         = (const float*)d_in[2];
    const int*   node_batch = (const int*)  d_in[3];
    const int*   neigh      = (const int*)  d_in[4];
    float*       out        = (float*)d_out;

    const int N = in_sizes[0] / EMB;   // 500000
    const int B = in_sizes[3];         // 100000

    __half *embh = nullptr, *h1h = nullptr, *aggh = nullptr;
    cudaGetSymbolAddress((void**)&embh, g_embh);
    cudaGetSymbolAddress((void**)&h1h,  g_h1h);
    cudaGetSymbolAddress((void**)&aggh, g_aggh);

    // emb fp32 -> fp16 (keeps gather working set L2-resident)
    cvt_f32_to_f16<<<4096, 256>>>(emb, embh, N * EMB / 4);

    // Layer 1
    agg_kernel<<<(N + 127) / 128, 128>>>(embh, nullptr, neigh, aggh, N);
    matvec_kernel<false, true><<<(N + 255) / 256, 256>>>(
        embh, aggh, nullptr, W1, h1h, N);

    // Layer 2
    agg_kernel<<<(B + 127) / 128, 128>>>(h1h, node_batch, neigh, aggh, B);
    matvec_kernel<true, false><<<(B + 255) / 256, 256>>>(
        h1h, aggh, node_batch, W2, out, B);
}

// round 9
// speedup vs baseline: 1.3327x; 1.0119x over previous
#include <cuda_runtime.h>
#include <cuda_fp16.h>

#define EMB 32
#define K 10

// fp16 tables (device globals: allocation-free scratch)
__device__ __align__(16) __half g_embh[500000 * EMB];   // 32 MB
__device__ __align__(16) __half g_h1h [500000 * EMB];   // 32 MB
__device__ __align__(16) __half g_aggh[500096 * EMB];   // 32 MB (padded)

// sm_103a packed fp32 pair FMA
__device__ __forceinline__ void ffma2(unsigned long long& acc,
                                      unsigned long long a, unsigned long long b)
{ asm("fma.rn.f32x2 %0, %1, %2, %0;" : "+l"(acc) : "l"(a), "l"(b)); }

__device__ __forceinline__ unsigned long long pack2(float lo, float hi)
{ unsigned long long r; asm("mov.b64 %0, {%1, %2};" : "=l"(r) : "f"(lo), "f"(hi)); return r; }

// unpack 8 halves (one uint4) -> 8 floats
__device__ __forceinline__ void cvt8(uint4 v, float* f)
{
    const __half2* h = reinterpret_cast<const __half2*>(&v);
    #pragma unroll
    for (int i = 0; i < 4; i++) {
        float2 t = __half22float2(h[i]);
        f[2 * i]     = t.x;
        f[2 * i + 1] = t.y;
    }
}

// ---- fp32 -> fp16 table conversion ----
__global__ __launch_bounds__(256)
void cvt_f32_to_f16(const float* __restrict__ src, __half* __restrict__ dst, int n4)
{
    int i = blockIdx.x * blockDim.x + threadIdx.x;
    int stride = gridDim.x * blockDim.x;
    const float4* s4 = reinterpret_cast<const float4*>(src);
    __half2* d2 = reinterpret_cast<__half2*>(dst);
    for (; i < n4; i += stride) {
        float4 v = s4[i];
        d2[2 * i]     = __floats2half2_rn(v.x, v.y);
        d2[2 * i + 1] = __floats2half2_rn(v.z, v.w);
    }
}

// ======================================================================
// AGG kernel: agg[t] = mean_k feat[neigh[id(t)][k]]  (fp16 in / fp16 out)
// ONE pass per warp (8 nodes), 32 nodes per 128-thread block:
// minimal per-warp latency chain, 4x grid for SM-level MLP.
// ======================================================================
__global__ __launch_bounds__(128, 8)
void agg_kernel(const __half* __restrict__ feat,
                const int*    __restrict__ node_ids,   // nullptr -> identity
                const int*    __restrict__ neigh,
                __half*       __restrict__ agg,        // [>=n, 32]
                int n)
{
    const int lane  = threadIdx.x & 31;
    const int wrp   = threadIdx.x >> 5;
    const int grp8  = lane >> 2;     // this lane's node within the warp's 8
    const int c2    = lane & 3;      // 16B chunk within the 64B fp16 row
    const int nbase = blockIdx.x * 32 + wrp * 8;

    // node id for this lane's group (lanes of a group read the same id: broadcast)
    int g   = nbase + grp8;
    int sid = (g < n) ? (node_ids ? node_ids[g] : g) : 0;

    // 10 neighbor ids (group-uniform addresses -> L1 broadcast)
    int nb[K];
    #pragma unroll
    for (int k = 0; k < K; k++)
        nb[k] = neigh[sid * K + k];

    // 10 independent LDG.128, all in flight
    uint4 raw[K];
    #pragma unroll
    for (int k = 0; k < K; k++)
        raw[k] = *(reinterpret_cast<const uint4*>(feat + nb[k] * EMB) + c2);

    float acc[8] = {0,0,0,0,0,0,0,0};
    #pragma unroll
    for (int k = 0; k < K; k++) {
        float f[8];
        cvt8(raw[k], f);
        #pragma unroll
        for (int i = 0; i < 8; i++) acc[i] += f[i];
    }

    if (g < n) {
        __half2 h[4];
        #pragma unroll
        for (int i = 0; i < 4; i++)
            h[i] = __floats2half2_rn(acc[2 * i] * 0.1f, acc[2 * i + 1] * 0.1f);
        *(reinterpret_cast<uint4*>(agg + g * EMB) + c2)
            = *reinterpret_cast<const uint4*>(h);
    }
}

// ======================================================================
// MATVEC kernel: out[t] = relu(W @ [self | agg])   thread-per-node
// acc-outer: 16 packed j-pair accumulators; W as j-pair table in smem.
// ======================================================================
template<bool SELF_GATHER, bool OUT_HALF>
__global__ __launch_bounds__(256, 4)
void matvec_kernel(const __half* __restrict__ feat,      // self source [*, 32]
                   const __half* __restrict__ agg,       // [n, 32]
                   const int*    __restrict__ node_ids,  // used if SELF_GATHER
                   const float*  __restrict__ W,         // [32, 64]
                   void*         __restrict__ outp,
                   int n)
{
    // Wts[i][jp] = (W[2jp][i], W[2jp+1][i]) packed
    __shared__ __align__(16) unsigned long long Wts[64 * 16];   // 8 KB

    for (int e = threadIdx.x; e < 64 * 16; e += 256) {
        int i  = e & 63;
        int jp = e >> 6;
        Wts[i * 16 + jp] = pack2(W[(2 * jp) * 64 + i], W[(2 * jp + 1) * 64 + i]);
    }
    __syncthreads();

    int t = blockIdx.x * 256 + threadIdx.x;
    if (t >= n) return;

    const __half* selfp = SELF_GATHER ? (feat + (size_t)node_ids[t] * EMB)
                                      : (feat + (size_t)t * EMB);
    const __half* aggp  = agg + (size_t)t * EMB;

    // Prefetch both rows: 8 independent LDG.128
    uint4 s[4], a[4];
    #pragma unroll
    for (int c = 0; c < 4; c++) s[c] = reinterpret_cast<const uint4*>(selfp)[c];
    #pragma unroll
    for (int c = 0; c < 4; c++) a[c] = reinterpret_cast<const uint4*>(aggp)[c];

    unsigned long long acc2[16];
    #pragma unroll
    for (int jp = 0; jp < 16; jp++) acc2[jp] = 0ull;

    auto do_chunk = [&](uint4 v, int ibase) {
        const __half2* h = reinterpret_cast<const __half2*>(&v);
        #pragma unroll
        for (int q = 0; q < 4; q++) {
            float2 f = __half22float2(h[q]);
            int i = ibase + 2 * q;
            unsigned long long dx = pack2(f.x, f.x);
            unsigned long long dy = pack2(f.y, f.y);
            const ulonglong2* ra = reinterpret_cast<const ulonglong2*>(&Wts[i * 16]);
            const ulonglong2* rb = reinterpret_cast<const ulonglong2*>(&Wts[(i + 1) * 16]);
            #pragma unroll
            for (int jp2 = 0; jp2 < 8; jp2++) {
                ulonglong2 wa = ra[jp2];          // uniform LDS.128 broadcast
                ulonglong2 wb = rb[jp2];
                ffma2(acc2[2 * jp2],     dx, wa.x);
                ffma2(acc2[2 * jp2 + 1], dx, wa.y);
                ffma2(acc2[2 * jp2],     dy, wb.x);
                ffma2(acc2[2 * jp2 + 1], dy, wb.y);
            }
        }
    };

    #pragma unroll
    for (int c = 0; c < 4; c++) do_chunk(s[c], c * 8);        // self: i 0..31
    #pragma unroll
    for (int c = 0; c < 4; c++) do_chunk(a[c], 32 + c * 8);   // agg:  i 32..63

    if (OUT_HALF) {
        __half2 h[16];
        #pragma unroll
        for (int jp = 0; jp < 16; jp++) {
            float lo, hi;
            asm("mov.b64 {%0, %1}, %2;" : "=f"(lo), "=f"(hi) : "l"(acc2[jp]));
            h[jp] = __floats2half2_rn(fmaxf(lo, 0.f), fmaxf(hi, 0.f));
        }
        __half* out = reinterpret_cast<__half*>(outp);
        const uint4* hv = reinterpret_cast<const uint4*>(h);
        #pragma unroll
        for (int c = 0; c < 4; c++)
            reinterpret_cast<uint4*>(out + (size_t)t * EMB)[c] = hv[c];
    } else {
        float* out = reinterpret_cast<float*>(outp) + (size_t)t * EMB;
        #pragma unroll
        for (int jp = 0; jp < 16; jp++) {
            float lo, hi;
            asm("mov.b64 {%0, %1}, %2;" : "=f"(lo), "=f"(hi) : "l"(acc2[jp]));
            out[2 * jp]     = fmaxf(lo, 0.f);
            out[2 * jp + 1] = fmaxf(hi, 0.f);
        }
    }
}

extern "C" void kernel_launch(void* const* d_in, const int* in_sizes, int n_in,
                              void* d_out, int out_size)
{
    // metadata order: emb, W1, W2, node_batch, neigh
    const float* emb        = (const float*)d_in[0];
    const float* W1         = (const float*)d_in[1];
    const float* W2         = (const float*)d_in[2];
    const int*   node_batch = (const int*)  d_in[3];
    const int*   neigh      = (const int*)  d_in[4];
    float*       out        = (float*)d_out;

    const int N = in_sizes[0] / EMB;   // 500000
    const int B = in_sizes[3];         // 100000

    __half *embh = nullptr, *h1h = nullptr, *aggh = nullptr;
    cudaGetSymbolAddress((void**)&embh, g_embh);
    cudaGetSymbolAddress((void**)&h1h,  g_h1h);
    cudaGetSymbolAddress((void**)&aggh, g_aggh);

    // emb fp32 -> fp16 (keeps gather working set L2-resident)
    cvt_f32_to_f16<<<4096, 256>>>(emb, embh, N * EMB / 4);

    // Layer 1  (32 nodes per agg block)
    agg_kernel<<<(N + 31) / 32, 128>>>(embh, nullptr, neigh, aggh, N);
    matvec_kernel<false, true><<<(N + 255) / 256, 256>>>(
        embh, aggh, nullptr, W1, h1h, N);

    // Layer 2
    agg_kernel<<<(B + 31) / 32, 128>>>(h1h, node_batch, neigh, aggh, B);
    matvec_kernel<true, false><<<(B + 255) / 256, 256>>>(
        h1h, aggh, node_batch, W2, out, B);
}

// round 10
// speedup vs baseline: 2.2606x; 1.6962x over previous
#include <cuda_runtime.h>
#include <cuda_fp16.h>

#define EMB 32
#define K 10

// fp16 tables (device globals: allocation-free scratch)
__device__ __align__(16) __half g_embh[500000 * EMB];   // 32 MB
__device__ __align__(16) __half g_h1h [500000 * EMB];   // 32 MB
__device__ __align__(16) __half g_aggh[500096 * EMB];   // 32 MB (padded)

// unpack 8 halves (one uint4) -> 8 floats
__device__ __forceinline__ void cvt8(uint4 v, float* f)
{
    const __half2* h = reinterpret_cast<const __half2*>(&v);
    #pragma unroll
    for (int i = 0; i < 4; i++) {
        float2 t = __half22float2(h[i]);
        f[2 * i]     = t.x;
        f[2 * i + 1] = t.y;
    }
}

// ---- fp32 -> fp16 table conversion ----
__global__ __launch_bounds__(256)
void cvt_f32_to_f16(const float* __restrict__ src, __half* __restrict__ dst, int n4)
{
    int i = blockIdx.x * blockDim.x + threadIdx.x;
    int stride = gridDim.x * blockDim.x;
    const float4* s4 = reinterpret_cast<const float4*>(src);
    __half2* d2 = reinterpret_cast<__half2*>(dst);
    for (; i < n4; i += stride) {
        float4 v = s4[i];
        d2[2 * i]     = __floats2half2_rn(v.x, v.y);
        d2[2 * i + 1] = __floats2half2_rn(v.z, v.w);
    }
}

// ======================================================================
// AGG kernel: agg[t] = mean_k feat[neigh[id(t)][k]]  (fp16 in / fp16 out)
// one pass per warp (8 nodes), warps fully independent
// ======================================================================
__global__ __launch_bounds__(128, 8)
void agg_kernel(const __half* __restrict__ feat,
                const int*    __restrict__ node_ids,   // nullptr -> identity
                const int*    __restrict__ neigh,
                __half*       __restrict__ agg,        // [>=n, 32]
                int n)
{
    const int lane  = threadIdx.x & 31;
    const int wrp   = threadIdx.x >> 5;
    const int grp8  = lane >> 2;
    const int c2    = lane & 3;
    const int nbase = blockIdx.x * 32 + wrp * 8;

    int g   = nbase + grp8;
    int sid = (g < n) ? (node_ids ? node_ids[g] : g) : 0;

    int nb[K];
    #pragma unroll
    for (int k = 0; k < K; k++)
        nb[k] = neigh[sid * K + k];

    uint4 raw[K];
    #pragma unroll
    for (int k = 0; k < K; k++)
        raw[k] = *(reinterpret_cast<const uint4*>(feat + nb[k] * EMB) + c2);

    float acc[8] = {0,0,0,0,0,0,0,0};
    #pragma unroll
    for (int k = 0; k < K; k++) {
        float f[8];
        cvt8(raw[k], f);
        #pragma unroll
        for (int i = 0; i < 8; i++) acc[i] += f[i];
    }

    if (g < n) {
        __half2 h[4];
        #pragma unroll
        for (int i = 0; i < 4; i++)
            h[i] = __floats2half2_rn(acc[2 * i] * 0.1f, acc[2 * i + 1] * 0.1f);
        *(reinterpret_cast<uint4*>(agg + g * EMB) + c2)
            = *reinterpret_cast<const uint4*>(h);
    }
}

// ======================================================================
// MATVEC via tensor cores: per warp D[32,32] = A[32,64] @ W^T
// A = [self | agg] fp16 staged in smem (pitch 72 halves: ldmatrix
// conflict-free), W held as 16 B-fragments in registers (fp16).
// ======================================================================
__device__ __forceinline__ void mma16816(float* c, const unsigned* a,
                                         unsigned b0, unsigned b1)
{
    asm volatile(
        "mma.sync.aligned.m16n8k16.row.col.f32.f16.f16.f32 "
        "{%0,%1,%2,%3}, {%4,%5,%6,%7}, {%8,%9}, {%0,%1,%2,%3};"
        : "+f"(c[0]), "+f"(c[1]), "+f"(c[2]), "+f"(c[3])
        : "r"(a[0]), "r"(a[1]), "r"(a[2]), "r"(a[3]), "r"(b0), "r"(b1));
}

#define APITCH 72   // halves per A row (144B: 16i mod 128 distinct -> conflict-free)

template<bool SELF_GATHER, bool OUT_HALF>
__global__ __launch_bounds__(128, 5)
void matvec_mma_kernel(const __half* __restrict__ feat,
                       const __half* __restrict__ agg,
                       const int*    __restrict__ node_ids,
                       const float*  __restrict__ W,       // [32 out, 64 in]
                       void*         __restrict__ outp,
                       int n)
{
    __shared__ __align__(16) __half As[128 * APITCH];   // 18.4 KB

    const int lane = threadIdx.x & 31;
    const int wrp  = threadIdx.x >> 5;
    const int g    = lane >> 2;      // group id 0..7
    const int tig  = lane & 3;       // thread-in-group
    const int nbase = blockIdx.x * 128 + wrp * 32;

    // ---- B fragments: b[kt][nt] covers W^T[k-tile, n-tile], fp32->fp16 ----
    unsigned b[4][4][2];
    #pragma unroll
    for (int kt = 0; kt < 4; kt++) {
        #pragma unroll
        for (int nt = 0; nt < 4; nt++) {
            int nrow = nt * 8 + g;          // output index j
            int k0   = kt * 16 + tig * 2;   // input index i
            float2 w0 = *reinterpret_cast<const float2*>(W + nrow * 64 + k0);
            float2 w1 = *reinterpret_cast<const float2*>(W + nrow * 64 + k0 + 8);
            __half2 h0 = __floats2half2_rn(w0.x, w0.y);
            __half2 h1 = __floats2half2_rn(w1.x, w1.y);
            b[kt][nt][0] = *reinterpret_cast<unsigned*>(&h0);
            b[kt][nt][1] = *reinterpret_cast<unsigned*>(&h1);
        }
    }

    // ---- stage A: 32 rows of [self(32) | agg(32)] halves ----
    #pragma unroll
    for (int p = 0; p < 4; p++) {
        int r  = p * 8 + g;                  // row within warp's 32
        int t  = nbase + r;
        int tc = min(t, n - 1);
        const __half* sp = SELF_GATHER
            ? (feat + (size_t)node_ids[tc] * EMB)
            : (feat + (size_t)tc * EMB);
        uint4 vs = *(reinterpret_cast<const uint4*>(sp) + tig);
        uint4 va = *(reinterpret_cast<const uint4*>(agg + (size_t)tc * EMB) + tig);
        __half* dst = &As[(wrp * 32 + r) * APITCH];
        *reinterpret_cast<uint4*>(dst + tig * 8)      = vs;   // self: cols 0..31
        *reinterpret_cast<uint4*>(dst + 32 + tig * 8) = va;   // agg: cols 32..63
    }
    __syncwarp();

    // ---- mma mainloop: 2 m-tiles x 4 n-tiles x 4 k-tiles ----
    float acc[2][4][4];
    #pragma unroll
    for (int mt = 0; mt < 2; mt++)
        #pragma unroll
        for (int nt = 0; nt < 4; nt++)
            #pragma unroll
            for (int q = 0; q < 4; q++) acc[mt][nt][q] = 0.f;

    #pragma unroll
    for (int kt = 0; kt < 4; kt++) {
        #pragma unroll
        for (int mt = 0; mt < 2; mt++) {
            // canonical x4 ldmatrix: lanes 0-15 -> rows, first 16B; 16-31 second
            int row  = wrp * 32 + mt * 16 + (lane & 15);
            int colh = kt * 16 + (lane >> 4) * 8;
            unsigned addr = (unsigned)__cvta_generic_to_shared(
                                &As[row * APITCH + colh]);
            unsigned a[4];
            asm volatile(
                "ldmatrix.sync.aligned.m8n8.x4.shared.b16 {%0,%1,%2,%3}, [%4];"
                : "=r"(a[0]), "=r"(a[1]), "=r"(a[2]), "=r"(a[3]) : "r"(addr));
            #pragma unroll
            for (int nt = 0; nt < 4; nt++)
                mma16816(acc[mt][nt], a, b[kt][nt][0], b[kt][nt][1]);
        }
    }

    // ---- epilogue: relu + store ----
    #pragma unroll
    for (int mt = 0; mt < 2; mt++) {
        #pragma unroll
        for (int nt = 0; nt < 4; nt++) {
            int r0  = nbase + mt * 16 + g;
            int r1  = r0 + 8;
            int col = nt * 8 + tig * 2;
            float c0 = fmaxf(acc[mt][nt][0], 0.f);
            float c1 = fmaxf(acc[mt][nt][1], 0.f);
            float c2v = fmaxf(acc[mt][nt][2], 0.f);
            float c3v = fmaxf(acc[mt][nt][3], 0.f);
            if (OUT_HALF) {
                __half* out = reinterpret_cast<__half*>(outp);
                if (r0 < n)
                    *reinterpret_cast<__half2*>(out + (size_t)r0 * EMB + col)
                        = __floats2half2_rn(c0, c1);
                if (r1 < n)
                    *reinterpret_cast<__half2*>(out + (size_t)r1 * EMB + col)
                        = __floats2half2_rn(c2v, c3v);
            } else {
                float* out = reinterpret_cast<float*>(outp);
                if (r0 < n)
                    *reinterpret_cast<float2*>(out + (size_t)r0 * EMB + col)
                        = make_float2(c0, c1);
                if (r1 < n)
                    *reinterpret_cast<float2*>(out + (size_t)r1 * EMB + col)
                        = make_float2(c2v, c3v);
            }
        }
    }
}

extern "C" void kernel_launch(void* const* d_in, const int* in_sizes, int n_in,
                              void* d_out, int out_size)
{
    // metadata order: emb, W1, W2, node_batch, neigh
    const float* emb        = (const float*)d_in[0];
    const float* W1         = (const float*)d_in[1];
    const float* W2         = (const float*)d_in[2];
    const int*   node_batch = (const int*)  d_in[3];
    const int*   neigh      = (const int*)  d_in[4];
    float*       out        = (float*)d_out;

    const int N = in_sizes[0] / EMB;   // 500000
    const int B = in_sizes[3];         // 100000

    __half *embh = nullptr, *h1h = nullptr, *aggh = nullptr;
    cudaGetSymbolAddress((void**)&embh, g_embh);
    cudaGetSymbolAddress((void**)&h1h,  g_h1h);
    cudaGetSymbolAddress((void**)&aggh, g_aggh);

    // emb fp32 -> fp16 (keeps gather working set L2-resident)
    cvt_f32_to_f16<<<4096, 256>>>(emb, embh, N * EMB / 4);

    // Layer 1
    agg_kernel<<<(N + 31) / 32, 128>>>(embh, nullptr, neigh, aggh, N);
    matvec_mma_kernel<false, true><<<(N + 127) / 128, 128>>>(
        embh, aggh, nullptr, W1, h1h, N);

    // Layer 2
    agg_kernel<<<(B + 31) / 32, 128>>>(h1h, node_batch, neigh, aggh, B);
    matvec_mma_kernel<true, false><<<(B + 127) / 128, 128>>>(
        h1h, aggh, node_batch, W2, out, B);
}

// round 11
// speedup vs baseline: 2.5442x; 1.1255x over previous
#include <cuda_runtime.h>
#include <cuda_fp16.h>

#define EMB 32
#define K 10
#define APITCH 72   // halves per A row (144B): ldmatrix conflict-free

// fp16 tables (device globals: allocation-free scratch)
__device__ __align__(16) __half g_embh[500000 * EMB];   // 32 MB
__device__ __align__(16) __half g_h1h [500000 * EMB];   // 32 MB

// unpack 8 halves (one uint4) -> 8 floats
__device__ __forceinline__ void cvt8(uint4 v, float* f)
{
    const __half2* h = reinterpret_cast<const __half2*>(&v);
    #pragma unroll
    for (int i = 0; i < 4; i++) {
        float2 t = __half22float2(h[i]);
        f[2 * i]     = t.x;
        f[2 * i + 1] = t.y;
    }
}

// ---- fp32 -> fp16 table conversion: 8 floats in, one uint4 out ----
__global__ __launch_bounds__(256)
void cvt_f32_to_f16(const float4* __restrict__ src, uint4* __restrict__ dst, int n8)
{
    int i = blockIdx.x * blockDim.x + threadIdx.x;
    int stride = gridDim.x * blockDim.x;
    for (; i < n8; i += stride) {
        float4 a = src[2 * i];
        float4 b = src[2 * i + 1];
        __half2 h[4];
        h[0] = __floats2half2_rn(a.x, a.y);
        h[1] = __floats2half2_rn(a.z, a.w);
        h[2] = __floats2half2_rn(b.x, b.y);
        h[3] = __floats2half2_rn(b.z, b.w);
        dst[i] = *reinterpret_cast<const uint4*>(h);
    }
}

// ======================================================================
// FUSED layer kernel: per warp D[32,32] = relu([self|agg(mean)] @ W^T)
//  - gather + mean written straight into the smem A tile (no agg table)
//  - HMMA m16n8k16 mainloop, W as fp16 B-fragments in registers
// ======================================================================
__device__ __forceinline__ void mma16816(float* c, const unsigned* a,
                                         unsigned b0, unsigned b1)
{
    asm volatile(
        "mma.sync.aligned.m16n8k16.row.col.f32.f16.f16.f32 "
        "{%0,%1,%2,%3}, {%4,%5,%6,%7}, {%8,%9}, {%0,%1,%2,%3};"
        : "+f"(c[0]), "+f"(c[1]), "+f"(c[2]), "+f"(c[3])
        : "r"(a[0]), "r"(a[1]), "r"(a[2]), "r"(a[3]), "r"(b0), "r"(b1));
}

template<bool SELF_GATHER, bool OUT_HALF>
__global__ __launch_bounds__(128, 5)
void sage_fused_kernel(const __half* __restrict__ feat,      // [*, 32] fp16
                       const int*    __restrict__ node_ids,  // if SELF_GATHER
                       const int*    __restrict__ neigh,     // [N_NODES, K]
                       const float*  __restrict__ W,         // [32 out, 64 in]
                       void*         __restrict__ outp,
                       int n)
{
    __shared__ __align__(16) __half As[128 * APITCH];   // 18.4 KB

    const int lane  = threadIdx.x & 31;
    const int wrp   = threadIdx.x >> 5;
    const int g     = lane >> 2;      // group 0..7 (one node per pass)
    const int tig   = lane & 3;       // 16B chunk within 64B row
    const int nbase = blockIdx.x * 128 + wrp * 32;

    // ---- PHASE A: gather self + mean(neigh) straight into As ----
    #pragma unroll
    for (int p = 0; p < 4; p++) {
        int r   = p * 8 + g;
        int t   = nbase + r;
        int tc  = min(t, n - 1);
        int sid = SELF_GATHER ? node_ids[tc] : tc;

        // self row chunk (independent of neighbor loads)
        uint4 vs = *(reinterpret_cast<const uint4*>(feat + (size_t)sid * EMB) + tig);

        // neighbor ids (group-uniform -> L1 broadcast)
        int nb[K];
        #pragma unroll
        for (int k = 0; k < K; k++)
            nb[k] = neigh[sid * K + k];

        // 10 independent LDG.128 in flight
        uint4 raw[K];
        #pragma unroll
        for (int k = 0; k < K; k++)
            raw[k] = *(reinterpret_cast<const uint4*>(feat + (size_t)nb[k] * EMB) + tig);

        float acc[8] = {0,0,0,0,0,0,0,0};
        #pragma unroll
        for (int k = 0; k < K; k++) {
            float f[8];
            cvt8(raw[k], f);
            #pragma unroll
            for (int i = 0; i < 8; i++) acc[i] += f[i];
        }

        __half2 h[4];
        #pragma unroll
        for (int i = 0; i < 4; i++)
            h[i] = __floats2half2_rn(acc[2 * i] * 0.1f, acc[2 * i + 1] * 0.1f);

        __half* dst = &As[(wrp * 32 + r) * APITCH];
        *reinterpret_cast<uint4*>(dst + tig * 8)      = vs;                         // self
        *reinterpret_cast<uint4*>(dst + 32 + tig * 8) = *reinterpret_cast<const uint4*>(h); // agg
    }
    __syncwarp();

    // ---- PHASE B: B fragments (fp32 W -> fp16), after gather to cap pressure ----
    unsigned b[4][4][2];
    #pragma unroll
    for (int kt = 0; kt < 4; kt++) {
        #pragma unroll
        for (int nt = 0; nt < 4; nt++) {
            int nrow = nt * 8 + g;
            int k0   = kt * 16 + tig * 2;
            float2 w0 = *reinterpret_cast<const float2*>(W + nrow * 64 + k0);
            float2 w1 = *reinterpret_cast<const float2*>(W + nrow * 64 + k0 + 8);
            __half2 h0 = __floats2half2_rn(w0.x, w0.y);
            __half2 h1 = __floats2half2_rn(w1.x, w1.y);
            b[kt][nt][0] = *reinterpret_cast<unsigned*>(&h0);
            b[kt][nt][1] = *reinterpret_cast<unsigned*>(&h1);
        }
    }

    // ---- PHASE C: mma mainloop (2 m-tiles x 4 n-tiles x 4 k-tiles) ----
    float acc[2][4][4];
    #pragma unroll
    for (int mt = 0; mt < 2; mt++)
        #pragma unroll
        for (int nt = 0; nt < 4; nt++)
            #pragma unroll
            for (int q = 0; q < 4; q++) acc[mt][nt][q] = 0.f;

    #pragma unroll
    for (int kt = 0; kt < 4; kt++) {
        #pragma unroll
        for (int mt = 0; mt < 2; mt++) {
            int row  = wrp * 32 + mt * 16 + (lane & 15);
            int colh = kt * 16 + (lane >> 4) * 8;
            unsigned addr = (unsigned)__cvta_generic_to_shared(
                                &As[row * APITCH + colh]);
            unsigned a[4];
            asm volatile(
                "ldmatrix.sync.aligned.m8n8.x4.shared.b16 {%0,%1,%2,%3}, [%4];"
                : "=r"(a[0]), "=r"(a[1]), "=r"(a[2]), "=r"(a[3]) : "r"(addr));
            #pragma unroll
            for (int nt = 0; nt < 4; nt++)
                mma16816(acc[mt][nt], a, b[kt][nt][0], b[kt][nt][1]);
        }
    }

    // ---- PHASE D: relu + store ----
    #pragma unroll
    for (int mt = 0; mt < 2; mt++) {
        #pragma unroll
        for (int nt = 0; nt < 4; nt++) {
            int r0  = nbase + mt * 16 + g;
            int r1  = r0 + 8;
            int col = nt * 8 + tig * 2;
            float c0  = fmaxf(acc[mt][nt][0], 0.f);
            float c1  = fmaxf(acc[mt][nt][1], 0.f);
            float c2v = fmaxf(acc[mt][nt][2], 0.f);
            float c3v = fmaxf(acc[mt][nt][3], 0.f);
            if (OUT_HALF) {
                __half* out = reinterpret_cast<__half*>(outp);
                if (r0 < n)
                    *reinterpret_cast<__half2*>(out + (size_t)r0 * EMB + col)
                        = __floats2half2_rn(c0, c1);
                if (r1 < n)
                    *reinterpret_cast<__half2*>(out + (size_t)r1 * EMB + col)
                        = __floats2half2_rn(c2v, c3v);
            } else {
                float* out = reinterpret_cast<float*>(outp);
                if (r0 < n)
                    *reinterpret_cast<float2*>(out + (size_t)r0 * EMB + col)
                        = make_float2(c0, c1);
                if (r1 < n)
                    *reinterpret_cast<float2*>(out + (size_t)r1 * EMB + col)
                        = make_float2(c2v, c3v);
            }
        }
    }
}

extern "C" void kernel_launch(void* const* d_in, const int* in_sizes, int n_in,
                              void* d_out, int out_size)
{
    // metadata order: emb, W1, W2, node_batch, neigh
    const float* emb        = (const float*)d_in[0];
    const float* W1         = (const float*)d_in[1];
    const float* W2         = (const float*)d_in[2];
    const int*   node_batch = (const int*)  d_in[3];
    const int*   neigh      = (const int*)  d_in[4];
    float*       out        = (float*)d_out;

    const int N = in_sizes[0] / EMB;   // 500000
    const int B = in_sizes[3];         // 100000

    __half *embh = nullptr, *h1h = nullptr;
    cudaGetSymbolAddress((void**)&embh, g_embh);
    cudaGetSymbolAddress((void**)&h1h,  g_h1h);

    // emb fp32 -> fp16 (keeps gather working set L2-resident)
    cvt_f32_to_f16<<<4096, 256>>>((const float4*)emb, (uint4*)embh, N * EMB / 8);

    // Layer 1: h1 = relu([emb | mean(emb[neigh])] @ W1^T)  (fused, fp16 out)
    sage_fused_kernel<false, true><<<(N + 127) / 128, 128>>>(
        embh, nullptr, neigh, W1, h1h, N);

    // Layer 2: out = relu([h1[nb] | mean(h1[neigh[nb]])] @ W2^T)  (fused, fp32 out)
    sage_fused_kernel<true, false><<<(B + 127) / 128, 128>>>(
        h1h, node_batch, neigh, W2, out, B);
}